// round 3
// baseline (speedup 1.0000x reference)
#include <cuda_runtime.h>
#include <math.h>

// Q_MultiHeadedAttention: quantum attention collapsed to pure 2x2 Heisenberg
// algebra. SEQ=4, D=8, NQ=3. Output [4,3] float32.
//
//   u = Rz(tz)Ry(ty)Rx(tx)  =>  u^dag Z u = cx*cy*Z + cy*sx*Y - sy*X
//   Encoded rows are REAL: Z_t = (cx*cy*d_t - 2*sy*c_t) / n2
//     d_t = sum x_a^2 - x_{a+s}^2 ,  c_t = sum x_a*x_{a+s}  (s = qubit stride)
//   phi_i = (pi/6)(sum_t Zq_i[t] + sum_t Zq_i[t]*Zk0[t])     (Sk == 1 in fp32)
//   Output observable acts on qubit t only:
//     B_t = uv_t^dag ( c^2 Z + c s Y - s X ) uv_t,  (c,s)=cos/sin(phi/2)
//     Zout_t = ( c^2*PZ_t + c*s*PY_t - s*PX_t ) / n2_v
//     P*_t = G00*dv_t + 2*ReG01*cv_t,  G = uv_t^dag P uv_t  (phi-independent)
//   out[i,t] = (Zout_t + 1)/2

#define W_MUL 0.6324555320336759f
#define PI_F  3.14159265358979323846f

struct c2x2 { float2 m[2][2]; };

__device__ __forceinline__ float2 cmul(float2 a, float2 b) {
    return make_float2(a.x * b.x - a.y * b.y, a.x * b.y + a.y * b.x);
}

// u = Rz(wz) @ Ry(wy) @ Rx(wx)
__device__ __forceinline__ void make_u(float wx, float wy, float wz, c2x2& u) {
    float c0, s0, c1, s1, c2, s2;
    __sincosf(wx * 0.5f, &s0, &c0);
    __sincosf(wy * 0.5f, &s1, &c1);
    __sincosf(wz * 0.5f, &s2, &c2);
    float2 M00 = make_float2( c1 * c0,  s1 * s0);
    float2 M01 = make_float2(-s1 * c0, -c1 * s0);
    float2 M10 = make_float2( s1 * c0, -c1 * s0);
    float2 M11 = make_float2( c1 * c0, -s1 * s0);
    float2 e0 = make_float2(c2, -s2);
    float2 e1 = make_float2(c2,  s2);
    u.m[0][0] = cmul(e0, M00); u.m[0][1] = cmul(e0, M01);
    u.m[1][0] = cmul(e1, M10); u.m[1][1] = cmul(e1, M11);
}

// d_t, c_t bilinears + squared norm for a row (takes raw values, abs inside)
__device__ __forceinline__ void dc_row(const float4 lo, const float4 hi,
                                       float d[3], float c[3], float* n2o) {
    float x[8] = { fabsf(lo.x), fabsf(lo.y), fabsf(lo.z), fabsf(lo.w),
                   fabsf(hi.x), fabsf(hi.y), fabsf(hi.z), fabsf(hi.w) };
    float n2 = 0.f;
    #pragma unroll
    for (int a = 0; a < 8; a++) n2 += x[a] * x[a];
    *n2o = n2;
    #pragma unroll
    for (int t = 0; t < 3; t++) {
        int s = 1 << (2 - t);
        float dd = 0.f, cc = 0.f;
        #pragma unroll
        for (int a = 0; a < 8; a++) {
            if (a & s) continue;
            dd += x[a] * x[a] - x[a + s] * x[a + s];
            cc += x[a] * x[a + s];
        }
        d[t] = dd; c[t] = cc;
    }
}

// Z_t from (d,c,n2) and circuit weights w[9]
__device__ __forceinline__ void z_from_dc(const float d[3], const float c[3],
                                          float n2, const float w[9], float Z[3]) {
    float inv2 = __frcp_rn(n2);   // == 1/(sqrt(n2)+1e-12)^2 to fp32 precision
    #pragma unroll
    for (int t = 0; t < 3; t++) {
        float tx = w[3 * t] * W_MUL, ty = w[3 * t + 1] * W_MUL;
        float cx = __cosf(tx);
        float sy, cy;
        __sincosf(ty, &sy, &cy);
        Z[t] = (cx * cy * d[t] - 2.f * sy * c[t]) * inv2;
    }
}

__global__ void qattn_kernel(const float* __restrict__ q,
                             const float* __restrict__ k,
                             const float* __restrict__ v,
                             const float* __restrict__ wq,
                             const float* __restrict__ wk,
                             const float* __restrict__ wv,
                             float* __restrict__ out) {
    int i = threadIdx.x;   // output row, 0..3
    if (i >= 4) return;

    // ---- hoist all global loads ----
    const float4* q4 = (const float4*)(q + i * 8);
    const float4* k4 = (const float4*)k;
    const float4* v4 = (const float4*)v;
    float4 qlo = q4[0], qhi = q4[1];
    float4 klo = k4[0], khi = k4[1];
    float4 vlo = v4[0], vhi = v4[1];
    float wqv[9], wkv[9], wvv[9];
    #pragma unroll
    for (int j = 0; j < 9; j++) { wqv[j] = wq[j]; wkv[j] = wk[j]; wvv[j] = wv[j]; }

    // ---- bilinears for q-row-i, k0, v0 (independent, overlap load latency) ----
    float dq[3], cq[3], nq2, dk[3], ck[3], nk2, dv[3], cv[3], nv2;
    dc_row(qlo, qhi, dq, cq, &nq2);
    dc_row(klo, khi, dk, ck, &nk2);
    dc_row(vlo, vhi, dv, cv, &nv2);

    // ---- Zq, Zk -> phi ----
    float Zq[3], Zk[3];
    z_from_dc(dq, cq, nq2, wqv, Zq);
    z_from_dc(dk, ck, nk2, wkv, Zk);
    float phi = (PI_F / 6.f) * (Zq[0] + Zq[1] + Zq[2]
                                + Zq[0] * Zk[0] + Zq[1] * Zk[1] + Zq[2] * Zk[2]);

    // ---- phi-independent: conjugated Paulis of Uv per qubit -> P{Z,Y,X}_t ----
    float inv2v = __frcp_rn(nv2);
    float PZ[3], PY[3], PX[3];
    #pragma unroll
    for (int t = 0; t < 3; t++) {
        c2x2 u;
        make_u(wvv[3 * t] * W_MUL, wvv[3 * t + 1] * W_MUL, wvv[3 * t + 2] * W_MUL, u);
        float2 u00 = u.m[0][0], u01 = u.m[0][1], u10 = u.m[1][0], u11 = u.m[1][1];
        // G = u^dag P u; need G00 (real) and Re G01 only (r is real for real x)
        // P = Z:
        float gz00 = (u00.x * u00.x + u00.y * u00.y) - (u10.x * u10.x + u10.y * u10.y);
        float gz01r = (u00.x * u01.x + u00.y * u01.y) - (u10.x * u11.x + u10.y * u11.y);
        // P = X:
        float gx00 = 2.f * (u00.x * u10.x + u00.y * u10.y);
        float gx01r = (u00.x * u11.x + u00.y * u11.y) + (u10.x * u01.x + u10.y * u01.y);
        // P = Y: G00 = 2 Im(conj(u00) u10); ReG01 = Im(conj(u00)u11) - Im(conj(u10)u01)
        float gy00 = 2.f * (u00.x * u10.y - u00.y * u10.x);
        float gy01r = (u00.x * u11.y - u00.y * u11.x) - (u10.x * u01.y - u10.y * u01.x);
        PZ[t] = gz00 * dv[t] + 2.f * gz01r * cv[t];
        PY[t] = gy00 * dv[t] + 2.f * gy01r * cv[t];
        PX[t] = gx00 * dv[t] + 2.f * gx01r * cv[t];
    }

    // ---- short phi-dependent tail ----
    float s, c;
    __sincosf(phi * 0.5f, &s, &c);
    float c2 = c * c, cs = c * s;
    #pragma unroll
    for (int t = 0; t < 3; t++) {
        float z = (c2 * PZ[t] + cs * PY[t] - s * PX[t]) * inv2v;
        out[i * 3 + t] = (z + 1.f) * 0.5f;
    }
}

extern "C" void kernel_launch(void* const* d_in, const int* in_sizes, int n_in,
                              void* d_out, int out_size) {
    const float* q  = (const float*)d_in[0];
    const float* k  = (const float*)d_in[1];
    const float* v  = (const float*)d_in[2];
    const float* wq = (const float*)d_in[3];
    const float* wk = (const float*)d_in[4];
    const float* wv = (const float*)d_in[5];
    float* out = (float*)d_out;
    qattn_kernel<<<1, 4>>>(q, k, v, wq, wk, wv, out);
}

// round 4
// speedup vs baseline: 1.1140x; 1.1140x over previous
#include <cuda_runtime.h>
#include <math.h>

// Q_MultiHeadedAttention: quantum attention collapsed to 2x2 Heisenberg
// algebra, element-parallel (12 threads = 4 rows x 3 output qubits).
//
//   u = Rz(tz)Ry(ty)Rx(tx)  =>  u^dag Z u = cx*cy*Z + cy*sx*Y - sy*X
//   Real encoded rows:  Z_t = (cx*cy*d_t - 2*sy*c_t) / n2
//     d_t = sum x_a^2 - x_{a+s}^2 ,  c_t = sum x_a*x_{a+s}   (s = 4>>t)
//   phi_i = (pi/6)(sum_t Zq_i[t] (1 + Zk0[t] wait-no: sum Zq + sum Zq*Zk))
//   Output observable acts on qubit t only:
//     Zout_t = ( c^2*PZ_t + c*s*PY_t - s*PX_t ) / n2_v , (c,s)=cos/sin(phi/2)
//     P*_t = G00*dv_t + 2*ReG01*cv_t,  G = uv_t^dag P uv_t
//   out[i,t] = (Zout_t + 1)/2
//   Sk = Sv = 1 to fp32 (unitary norm preservation; eps=1e-12 invisible).

#define W_MUL 0.6324555320336759f
#define PI_F  3.14159265358979323846f

// d_t, c_t bilinears + squared norm for a row (abs applied inside)
__device__ __forceinline__ void dc_row(const float4 lo, const float4 hi,
                                       float d[3], float c[3], float* n2o) {
    float x[8] = { fabsf(lo.x), fabsf(lo.y), fabsf(lo.z), fabsf(lo.w),
                   fabsf(hi.x), fabsf(hi.y), fabsf(hi.z), fabsf(hi.w) };
    float n2 = 0.f;
    #pragma unroll
    for (int a = 0; a < 8; a++) n2 += x[a] * x[a];
    *n2o = n2;
    #pragma unroll
    for (int t = 0; t < 3; t++) {
        int s = 1 << (2 - t);
        float dd = 0.f, cc = 0.f;
        #pragma unroll
        for (int a = 0; a < 8; a++) {
            if (a & s) continue;
            dd += x[a] * x[a] - x[a + s] * x[a + s];
            cc += x[a] * x[a + s];
        }
        d[t] = dd; c[t] = cc;
    }
}

// Z_t (t=0..2) from bilinears and circuit weights w[9]
__device__ __forceinline__ void z_from_dc(const float d[3], const float c[3],
                                          float n2, const float w[9], float Z[3]) {
    float inv2 = __frcp_rn(n2);
    #pragma unroll
    for (int t = 0; t < 3; t++) {
        float cx = __cosf(w[3 * t] * W_MUL);
        float sy, cy;
        __sincosf(w[3 * t + 1] * W_MUL, &sy, &cy);
        Z[t] = (cx * cy * d[t] - 2.f * sy * c[t]) * inv2;
    }
}

__global__ void __launch_bounds__(32, 1)
qattn_kernel(const float* __restrict__ q,
             const float* __restrict__ k,
             const float* __restrict__ v,
             const float* __restrict__ wq,
             const float* __restrict__ wk,
             const float* __restrict__ wv,
             float* __restrict__ out) {
    int e = threadIdx.x;          // element id: e = i*3 + t, 0..11
    if (e >= 12) return;
    int i = e / 3;                // query row
    int t = e - 3 * i;            // output qubit

    // ---- hoist all global loads ----
    const float4* q4 = (const float4*)(q + i * 8);
    const float4* k4 = (const float4*)k;
    const float4* v4 = (const float4*)v;
    float4 qlo = __ldg(q4), qhi = __ldg(q4 + 1);
    float4 klo = __ldg(k4), khi = __ldg(k4 + 1);
    float4 vlo = __ldg(v4), vhi = __ldg(v4 + 1);
    float wqv[9], wkv[9];
    #pragma unroll
    for (int j = 0; j < 9; j++) { wqv[j] = __ldg(wq + j); wkv[j] = __ldg(wk + j); }
    float wvx = __ldg(wv + 3 * t)     * W_MUL;
    float wvy = __ldg(wv + 3 * t + 1) * W_MUL;
    float wvz = __ldg(wv + 3 * t + 2) * W_MUL;

    // ---- bilinears (independent ILP, overlaps load latency) ----
    float dq[3], cq[3], nq2, dk[3], ck[3], nk2, dv[3], cv[3], nv2;
    dc_row(qlo, qhi, dq, cq, &nq2);
    dc_row(klo, khi, dk, ck, &nk2);
    dc_row(vlo, vhi, dv, cv, &nv2);

    // ---- Zq, Zk -> phi_i ----
    float Zq[3], Zk[3];
    z_from_dc(dq, cq, nq2, wqv, Zq);
    z_from_dc(dk, ck, nk2, wkv, Zk);
    float phi = (PI_F / 6.f) * (Zq[0] + Zq[1] + Zq[2]
                                + Zq[0] * Zk[0] + Zq[1] * Zk[1] + Zq[2] * Zk[2]);

    // ---- phi-independent: u = Rz(wvz)Ry(wvy)Rx(wvx); G = u^dag P u on qubit t ----
    float c0, s0, c1, s1;
    __sincosf(wvx * 0.5f, &s0, &c0);
    __sincosf(wvy * 0.5f, &s1, &c1);
    // u (up to the Rz phase, which cancels in G00 and contributes phase to G01;
    // we need full u, so include Rz):
    float c2r, s2r;
    __sincosf(wvz * 0.5f, &s2r, &c2r);
    // M = Ry@Rx rows; u = diag(e^-i wz/2, e^+i wz/2) @ M
    float M00r = c1 * c0, M00i =  s1 * s0;
    float M01r = -s1 * c0, M01i = -c1 * s0;
    float M10r =  s1 * c0, M10i = -c1 * s0;
    float M11r =  c1 * c0, M11i = -s1 * s0;
    float u00r = c2r * M00r + s2r * M00i, u00i = -s2r * M00r + c2r * M00i;
    float u01r = c2r * M01r + s2r * M01i, u01i = -s2r * M01r + c2r * M01i;
    float u10r = c2r * M10r - s2r * M10i, u10i =  s2r * M10r + c2r * M10i;
    float u11r = c2r * M11r - s2r * M11i, u11i =  s2r * M11r + c2r * M11i;

    float gz00  = (u00r * u00r + u00i * u00i) - (u10r * u10r + u10i * u10i);
    float gz01r = (u00r * u01r + u00i * u01i) - (u10r * u11r + u10i * u11i);
    float gx00  = 2.f * (u00r * u10r + u00i * u10i);
    float gx01r = (u00r * u11r + u00i * u11i) + (u10r * u01r + u10i * u01i);
    float gy00  = 2.f * (u00r * u10i - u00i * u10r);
    float gy01r = (u00r * u11i - u00i * u11r) - (u10r * u01i - u10i * u01r);

    float inv2v = __frcp_rn(nv2);
    float PZ = (gz00 * dv[t] + 2.f * gz01r * cv[t]) * inv2v;
    float PY = (gy00 * dv[t] + 2.f * gy01r * cv[t]) * inv2v;
    float PX = (gx00 * dv[t] + 2.f * gx01r * cv[t]) * inv2v;

    // ---- short phi-dependent tail: one sincos, 3 FMA, store ----
    float sh, ch;
    __sincosf(phi * 0.5f, &sh, &ch);
    float z = ch * ch * PZ + ch * sh * PY - sh * PX;
    out[e] = (z + 1.f) * 0.5f;
}

extern "C" void kernel_launch(void* const* d_in, const int* in_sizes, int n_in,
                              void* d_out, int out_size) {
    const float* q  = (const float*)d_in[0];
    const float* k  = (const float*)d_in[1];
    const float* v  = (const float*)d_in[2];
    const float* wq = (const float*)d_in[3];
    const float* wk = (const float*)d_in[4];
    const float* wv = (const float*)d_in[5];
    float* out = (float*)d_out;
    qattn_kernel<<<1, 32>>>(q, k, v, wq, wk, wv, out);
}

// round 5
// speedup vs baseline: 1.4931x; 1.3403x over previous
#include <cuda_runtime.h>
#include <math.h>

// Q_MultiHeadedAttention: quantum attention collapsed to 2x2 Heisenberg
// algebra, element-parallel (12 threads = 4 rows x 3 output qubits).
//
//   u = Rz(tz)Ry(ty)Rx(tx)  =>  u^dag Z u = cx*cy*Z + cy*sx*Y - sy*X
//   Real encoded rows:  Z_t = (cx*cy*d_t - 2*sy*c_t) / n2
//     d_t = sum x_a^2 - x_{a+s}^2 ,  c_t = sum x_a*x_{a+s}   (s = 4>>t)
//   phi_i = (pi/6)(sum_t Zq_i[t] + sum_t Zq_i[t]*Zk0[t])
//   Output observable acts on qubit t only:
//     Zout_t = ( c^2*PZ_t + c*s*PY_t - s*PX_t ) / n2_v , (c,s)=cos/sin(phi/2)
//     P*_t = G00*dv_t + 2*ReG01*cv_t,  G = uv_t^dag P uv_t
//   out[i,t] = (Zout_t + 1)/2
//   Sk = Sv = 1 to fp32 (unitary norm preservation; eps=1e-12 invisible).

#define W_MUL 0.6324555320336759f
#define PI_F  3.14159265358979323846f

// d_t, c_t bilinears + squared norm for a row (abs applied inside)
__device__ __forceinline__ void dc_row(const float4 lo, const float4 hi,
                                       float d[3], float c[3], float* n2o) {
    float x[8] = { fabsf(lo.x), fabsf(lo.y), fabsf(lo.z), fabsf(lo.w),
                   fabsf(hi.x), fabsf(hi.y), fabsf(hi.z), fabsf(hi.w) };
    float n2 = 0.f;
    #pragma unroll
    for (int a = 0; a < 8; a++) n2 += x[a] * x[a];
    *n2o = n2;
    #pragma unroll
    for (int t = 0; t < 3; t++) {
        int s = 1 << (2 - t);
        float dd = 0.f, cc = 0.f;
        #pragma unroll
        for (int a = 0; a < 8; a++) {
            if (a & s) continue;
            dd += x[a] * x[a] - x[a + s] * x[a + s];
            cc += x[a] * x[a + s];
        }
        d[t] = dd; c[t] = cc;
    }
}

// Z_t (t=0..2) from bilinears and circuit weights w[9]
__device__ __forceinline__ void z_from_dc(const float d[3], const float c[3],
                                          float n2, const float w[9], float Z[3]) {
    float inv2 = __frcp_rn(n2);
    #pragma unroll
    for (int t = 0; t < 3; t++) {
        float cx = __cosf(w[3 * t] * W_MUL);
        float sy, cy;
        __sincosf(w[3 * t + 1] * W_MUL, &sy, &cy);
        Z[t] = (cx * cy * d[t] - 2.f * sy * c[t]) * inv2;
    }
}

__global__ void __launch_bounds__(32, 1)
qattn_kernel(const float* __restrict__ q,
             const float* __restrict__ k,
             const float* __restrict__ v,
             const float* __restrict__ wq,
             const float* __restrict__ wk,
             const float* __restrict__ wv,
             float* __restrict__ out) {
    int e = threadIdx.x;          // element id: e = i*3 + t, 0..11
    if (e >= 12) return;
    int i = e / 3;                // query row
    int t = e - 3 * i;            // output qubit

    // ---- issue ALL global loads back-to-back (max MLP, one DRAM round-trip) ----
    const float4* q4  = (const float4*)(q + i * 8);
    const float4* k4  = (const float4*)k;
    const float4* v4  = (const float4*)v;
    const float4* wq4 = (const float4*)wq;   // 9 floats: 2x float4 + tail
    const float4* wk4 = (const float4*)wk;
    float4 qlo = __ldg(q4),     qhi = __ldg(q4 + 1);
    float4 klo = __ldg(k4),     khi = __ldg(k4 + 1);
    float4 vlo = __ldg(v4),     vhi = __ldg(v4 + 1);
    float4 wqa = __ldg(wq4),    wqb = __ldg(wq4 + 1);
    float4 wka = __ldg(wk4),    wkb = __ldg(wk4 + 1);
    float  wq8 = __ldg(wq + 8);
    float  wk8 = __ldg(wk + 8);
    float  wvx = __ldg(wv + 3 * t)     * W_MUL;
    float  wvy = __ldg(wv + 3 * t + 1) * W_MUL;
    float  wvz = __ldg(wv + 3 * t + 2) * W_MUL;

    float wqv[9] = { wqa.x, wqa.y, wqa.z, wqa.w, wqb.x, wqb.y, wqb.z, wqb.w, wq8 };
    float wkv[9] = { wka.x, wka.y, wka.z, wka.w, wkb.x, wkb.y, wkb.z, wkb.w, wk8 };

    // ---- phi critical path first: Zq, Zk -> phi_i ----
    float dq[3], cq[3], nq2, dk[3], ck[3], nk2;
    dc_row(qlo, qhi, dq, cq, &nq2);
    dc_row(klo, khi, dk, ck, &nk2);
    float Zq[3], Zk[3];
    z_from_dc(dq, cq, nq2, wqv, Zq);
    z_from_dc(dk, ck, nk2, wkv, Zk);
    float phi = (PI_F / 6.f) * (Zq[0] + Zq[1] + Zq[2]
                                + Zq[0] * Zk[0] + Zq[1] * Zk[1] + Zq[2] * Zk[2]);
    float sh, ch;
    __sincosf(phi * 0.5f, &sh, &ch);

    // ---- phi-independent v-side (overlaps under the phi chain) ----
    float dv[3], cv[3], nv2;
    dc_row(vlo, vhi, dv, cv, &nv2);

    // u = Rz(wvz)Ry(wvy)Rx(wvx);  G = u^dag P u on qubit t
    float c0, s0, c1, s1, c2r, s2r;
    __sincosf(wvx * 0.5f, &s0, &c0);
    __sincosf(wvy * 0.5f, &s1, &c1);
    __sincosf(wvz * 0.5f, &s2r, &c2r);
    float M00r =  c1 * c0, M00i =  s1 * s0;
    float M01r = -s1 * c0, M01i = -c1 * s0;
    float M10r =  s1 * c0, M10i = -c1 * s0;
    float M11r =  c1 * c0, M11i = -s1 * s0;
    float u00r = c2r * M00r + s2r * M00i, u00i = -s2r * M00r + c2r * M00i;
    float u01r = c2r * M01r + s2r * M01i, u01i = -s2r * M01r + c2r * M01i;
    float u10r = c2r * M10r - s2r * M10i, u10i =  s2r * M10r + c2r * M10i;
    float u11r = c2r * M11r - s2r * M11i, u11i =  s2r * M11r + c2r * M11i;

    float gz00  = (u00r * u00r + u00i * u00i) - (u10r * u10r + u10i * u10i);
    float gz01r = (u00r * u01r + u00i * u01i) - (u10r * u11r + u10i * u11i);
    float gx00  = 2.f * (u00r * u10r + u00i * u10i);
    float gx01r = (u00r * u11r + u00i * u11i) + (u10r * u01r + u10i * u01i);
    float gy00  = 2.f * (u00r * u10i - u00i * u10r);
    float gy01r = (u00r * u11i - u00i * u11r) - (u10r * u01i - u10i * u01r);

    float inv2v = __frcp_rn(nv2);
    float PZ = (gz00 * dv[t] + 2.f * gz01r * cv[t]) * inv2v;
    float PY = (gy00 * dv[t] + 2.f * gy01r * cv[t]) * inv2v;
    float PX = (gx00 * dv[t] + 2.f * gx01r * cv[t]) * inv2v;

    // ---- tail: 3 FMA, store ----
    float z = ch * ch * PZ + ch * sh * PY - sh * PX;
    out[e] = (z + 1.f) * 0.5f;
}

extern "C" void kernel_launch(void* const* d_in, const int* in_sizes, int n_in,
                              void* d_out, int out_size) {
    const float* q  = (const float*)d_in[0];
    const float* k  = (const float*)d_in[1];
    const float* v  = (const float*)d_in[2];
    const float* wq = (const float*)d_in[3];
    const float* wk = (const float*)d_in[4];
    const float* wv = (const float*)d_in[5];
    float* out = (float*)d_out;
    qattn_kernel<<<1, 32>>>(q, k, v, wq, wk, wv, out);
}